// round 10
// baseline (speedup 1.0000x reference)
#include <cuda_runtime.h>
#include <cuda_bf16.h>
#include <math.h>

#define B_   2
#define T_   4
#define HH   256
#define WW   256
#define SP_  64
#define NH   7
#define NN   49
#define CE   512
#define DD   128
#define TEMP_ 0.07f

// ---------------- scratch ----------------
__device__ float g_ws   [B_*T_*NN*SP_];
__device__ float g_qpart[4][B_*T_*NN*DD];
__device__ float g_qsp  [B_*T_*SP_*DD];
__device__ float g_E    [6*SP_*SP_];
__device__ float g_rs   [6*SP_];
__device__ float g_csp  [6*8*SP_];
__device__ unsigned g_barcnt[2];   // monotonic, replay-safe

// ---------------- 1. fused: ws histograms + proj K-split ----------------
__global__ void fused_in_kernel(const int* __restrict__ sp_mask,
                                const float* __restrict__ feats,
                                const float* __restrict__ Wh,
                                float* __restrict__ out, int write_loss) {
    int bx = blockIdx.x;
    int tid = threadIdx.x;
    if (bx == 0 && tid == 0 && write_loss) out[0] = 0.f;
    if (bx < 392) {
        int w  = bx % NN;
        int bt = bx / NN;
        int wy = w / NH, wx = w % NH;
        int y0 = wy * 32, x0 = wx * 32;
        __shared__ float hist[2][SP_];
        if (tid < 2 * SP_) hist[tid >> 6][tid & 63] = 0.f;
        __syncthreads();
        int par = (tid >> 5) & 1;
        const int* base = sp_mask + bt * (HH * WW);
        #pragma unroll
        for (int k = 0; k < 4; k++) {
            int idx = (tid + k * 256) * 4;       // 4 consecutive pixels
            int py = idx >> 6, px = idx & 63;
            int y = y0 + py;
            float cy = (y >= 32 && y < 224) ? 0.5f : 1.0f;
            int4 s4 = *(const int4*)(base + y * WW + x0 + px);
            int xb = x0 + px;
            float cx0 = (xb     >= 32 && xb     < 224) ? 0.5f : 1.0f;
            float cx1 = (xb + 1 >= 32 && xb + 1 < 224) ? 0.5f : 1.0f;
            float cx2 = (xb + 2 >= 32 && xb + 2 < 224) ? 0.5f : 1.0f;
            float cx3 = (xb + 3 >= 32 && xb + 3 < 224) ? 0.5f : 1.0f;
            atomicAdd(&hist[par][s4.x], cy * cx0);
            atomicAdd(&hist[par][s4.y], cy * cx1);
            atomicAdd(&hist[par][s4.z], cy * cx2);
            atomicAdd(&hist[par][s4.w], cy * cx3);
        }
        __syncthreads();
        if (tid < SP_) g_ws[(bt * NN + w) * SP_ + tid] = hist[0][tid] + hist[1][tid];
    } else {
        int pid = bx - 392;
        int n   = pid % NN;
        int kq  = pid / NN;
        __shared__ float sf[2][128][4];
        __shared__ float partr[2][8][DD];
        {
            int bb = tid >> 7, row = tid & 127;
            const float4* src = (const float4*)feats + ((size_t)(bb * NN + n) * CE + kq * 128 + row);
            *(float4*)&sf[bb][row][0] = *src;
        }
        __syncthreads();
        int ch = tid >> 7, d = tid & 127;
        float acc[2][4] = {};
        const float* wp = Wh + (size_t)(kq * 128 + ch * 64) * DD + d;
        #pragma unroll
        for (int cc = 0; cc < 2; cc++) {
            float wv[32];
            #pragma unroll
            for (int u = 0; u < 32; u++)
                wv[u] = wp[(size_t)(cc * 32 + u) * DD];
            #pragma unroll
            for (int u = 0; u < 32; u++) {
                int cl = cc * 32 + u;
                float4 f0 = *(const float4*)&sf[0][ch * 64 + cl][0];
                float4 f1 = *(const float4*)&sf[1][ch * 64 + cl][0];
                acc[0][0] = fmaf(f0.x, wv[u], acc[0][0]);
                acc[0][1] = fmaf(f0.y, wv[u], acc[0][1]);
                acc[0][2] = fmaf(f0.z, wv[u], acc[0][2]);
                acc[0][3] = fmaf(f0.w, wv[u], acc[0][3]);
                acc[1][0] = fmaf(f1.x, wv[u], acc[1][0]);
                acc[1][1] = fmaf(f1.y, wv[u], acc[1][1]);
                acc[1][2] = fmaf(f1.z, wv[u], acc[1][2]);
                acc[1][3] = fmaf(f1.w, wv[u], acc[1][3]);
            }
        }
        #pragma unroll
        for (int b = 0; b < 2; b++)
            #pragma unroll
            for (int t = 0; t < 4; t++)
                partr[ch][b * 4 + t][d] = acc[b][t];
        __syncthreads();
        if (ch == 0) {
            #pragma unroll
            for (int r = 0; r < 8; r++)
                g_qpart[kq][((size_t)r * NN + n) * DD + d] = partr[0][r][d] + partr[1][r][d];
        }
    }
}

// ---------------- grid barrier ----------------
#define NBLK 64
__device__ __forceinline__ void gridbar(int slot) {
    __syncthreads();
    __threadfence();
    if (threadIdx.x == 0) {
        unsigned my = atomicAdd(&g_barcnt[slot], 1u) + 1u;
        unsigned target = ((my + NBLK - 1u) / NBLK) * NBLK;
        while (*(volatile unsigned*)&g_barcnt[slot] < target) { }
    }
    __syncthreads();
    __threadfence();
}

// ---------------- 2. mega tail ----------------
#define ESTRIDE 65
#define BSTRIDE 68
// chain: 3*64*65 + 2*4*68 + 384 + 4 = 13412 floats; qsp 9524; as1 9864
#define SMEM_MEGA (13440 * 4)

// 4x64 @ 64x64: Out[r][m] = (sum_k In[r][k] * E[k][m or m][k]) * outScale[m]
__device__ __forceinline__ void mm4v(const float* __restrict__ In,
                                     const float* __restrict__ E,
                                     bool colAcc,
                                     const float* __restrict__ outScale,
                                     float* __restrict__ Out) {
    int tid = threadIdx.x;
    int r = tid >> 6, m = tid & 63;
    const float* ap = In + r * BSTRIDE;
    float acc0 = 0.f, acc1 = 0.f;
    if (colAcc) {
        const float* ep = E + m * ESTRIDE;
        #pragma unroll
        for (int k = 0; k < 32; k++) {
            acc0 = fmaf(ap[k],      ep[k],      acc0);
            acc1 = fmaf(ap[k + 32], ep[k + 32], acc1);
        }
    } else {
        #pragma unroll
        for (int k = 0; k < 32; k++) {
            acc0 = fmaf(ap[k],      E[k * ESTRIDE + m],        acc0);
            acc1 = fmaf(ap[k + 32], E[(k + 32) * ESTRIDE + m], acc1);
        }
    }
    float sc = outScale ? outScale[m] : 1.0f;
    __syncthreads();
    Out[r * BSTRIDE + m] = (acc0 + acc1) * sc;
    __syncthreads();
}

__global__ void mega_kernel(float* __restrict__ out, int aa_base, int write_loss) {
    extern __shared__ float sm[];
    int bx  = blockIdx.x;     // 0..63
    int tid = threadIdx.x;

    // ======== phase 1: qsp (blocks 0..31) ========
    if (bx < 32) {
        int bt = bx >> 2;
        int dq = bx & 3;
        float (*sq)[DD]  = (float(*)[DD]) sm;
        float (*sw)[SP_] = (float(*)[SP_])(sm + 6272);
        float* sinv = sm + 9408;
        float* sden = sm + 9460;
        {
            const float4* p0 = (const float4*)(g_qpart[0] + (size_t)bt * NN * DD);
            const float4* p1 = (const float4*)(g_qpart[1] + (size_t)bt * NN * DD);
            const float4* p2 = (const float4*)(g_qpart[2] + (size_t)bt * NN * DD);
            const float4* p3 = (const float4*)(g_qpart[3] + (size_t)bt * NN * DD);
            float* sqf = sm;
            for (int i = tid; i < 1568; i += 256) {
                float4 a = p0[i], b = p1[i], c = p2[i], d = p3[i];
                float4 r;
                r.x = a.x + b.x + c.x + d.x;
                r.y = a.y + b.y + c.y + d.y;
                r.z = a.z + b.z + c.z + d.z;
                r.w = a.w + b.w + c.w + d.w;
                *(float4*)(sqf + i * 4) = r;
            }
            const float4* pw = (const float4*)(g_ws + (size_t)bt * NN * SP_);
            float* swf = sm + 6272;
            for (int i = tid; i < 784; i += 256)
                *(float4*)(swf + i * 4) = pw[i];
        }
        __syncthreads();
        int wid = tid >> 5, lane = tid & 31;
        for (int n = wid; n < NN; n += 8) {
            float v0 = sq[n][lane], v1 = sq[n][lane + 32],
                  v2 = sq[n][lane + 64], v3 = sq[n][lane + 96];
            float ss = v0 * v0 + v1 * v1 + v2 * v2 + v3 * v3;
            #pragma unroll
            for (int o = 16; o > 0; o >>= 1) ss += __shfl_xor_sync(0xffffffffu, ss, o);
            if (lane == 0) sinv[n] = 1.0f / fmaxf(sqrtf(ss), 1e-12f);
        }
        if (tid < SP_) {
            float s = 0.f;
            for (int n = 0; n < NN; n++) s += sw[n][tid];
            sden[tid] = 1.0f / (s + 1e-20f);
        }
        __syncthreads();
        for (int i = tid; i < NN * SP_; i += 256) {
            int n = i >> 6, s = i & 63;
            sw[n][s] *= sinv[n] * sden[s];
        }
        __syncthreads();
        int d  = tid & 31;
        int dd = dq * 32 + d;
        int sg = tid >> 5;
        float acc[8] = {};
        for (int n = 0; n < NN; n++) {
            float qv = sq[n][dd];
            #pragma unroll
            for (int i = 0; i < 8; i++)
                acc[i] = fmaf(sw[n][sg * 8 + i], qv, acc[i]);
        }
        #pragma unroll
        for (int i = 0; i < 8; i++)
            g_qsp[((size_t)bt * SP_ + sg * 8 + i) * DD + dd] = acc[i];
    }

    gridbar(0);

    // ======== phase 2: as1 (blocks 0..47) ========
    if (bx < 48) {
        int job = bx >> 3;
        int rb  = bx & 7;
        int r0  = rb * 8;
        int b = job / 3, t = job % 3;
        const float* X = g_qsp + (size_t)(b * T_ + t)     * SP_ * DD;
        const float* Y = g_qsp + (size_t)(b * T_ + t + 1) * SP_ * DD;
        float (*sYt)[65] = (float(*)[65])sm;
        float (*sXr)[DD] = (float(*)[DD])(sm + 8320);
        float (*sE)[65]  = (float(*)[65])(sm + 9344);
        {
            const float4* Y4 = (const float4*)Y;
            for (int i = tid; i < 2048; i += 256) {
                int m = i >> 5, k4 = i & 31;
                float4 v = Y4[i];
                sYt[k4 * 4 + 0][m] = v.x;
                sYt[k4 * 4 + 1][m] = v.y;
                sYt[k4 * 4 + 2][m] = v.z;
                sYt[k4 * 4 + 3][m] = v.w;
            }
            const float4* X4 = (const float4*)(X + (size_t)r0 * DD);
            int r = tid >> 5, k4 = tid & 31;
            float4 v = X4[r * 32 + k4];
            *(float4*)&sXr[r][k4 * 4] = v;
        }
        __syncthreads();
        int m  = tid & 63;
        int lr = (tid >> 6) * 2;
        float a0 = 0.f, a1 = 0.f;
        #pragma unroll 8
        for (int k = 0; k < DD; k++) {
            float yv = sYt[k][m];
            a0 = fmaf(sXr[lr][k],     yv, a0);
            a1 = fmaf(sXr[lr + 1][k], yv, a1);
        }
        float e0 = expf(a0 * (1.0f / TEMP_)) - 1.0f;
        float e1 = expf(a1 * (1.0f / TEMP_)) - 1.0f;
        e0 *= e0; e1 *= e1;
        sE[lr][m] = e0; sE[lr + 1][m] = e1;
        g_E[(size_t)job * 4096 + (r0 + lr) * 64 + m]     = e0;
        g_E[(size_t)job * 4096 + (r0 + lr + 1) * 64 + m] = e1;
        __syncthreads();
        if (tid < 8) {
            float s = 0.f;
            for (int j = 0; j < 64; j++) s += sE[tid][j];
            g_rs[job * 64 + r0 + tid] = s;
        } else if (tid >= 64 && tid < 128) {
            int c = tid - 64;
            float s = 0.f;
            #pragma unroll
            for (int r = 0; r < 8; r++) s += sE[r][c];
            g_csp[(job * 8 + rb) * 64 + c] = s;
        }
    }

    gridbar(1);

    // ======== phase 3: chain (all 64 blocks; kind = aa1 | aa2) ========
    {
        float* E0s   = sm;
        float* E1s   = sm + 1 * 64 * ESTRIDE;
        float* E2s   = sm + 2 * 64 * ESTRIDE;
        float* buf0  = sm + 3 * 64 * ESTRIDE;      // 12480
        float* buf1  = buf0 + 4 * BSTRIDE;         // 12752
        float* sinvC = buf1 + 4 * BSTRIDE;         // 13024 [384]
        float* slloss = sinvC + 384;               // 13408 [4]
        int kind = bx >> 5;                 // 0: aa1, 1: aa2
        int b    = (bx >> 4) & 1;
        int r0   = (bx & 15) * 4;
        int j0   = b * 3;

        // scale table: rinv0..2 at 0/64/128, cinv0..2 at 192/256/320
        for (int i = tid; i < 384; i += 256) {
            int kk = i >> 6, idx = i & 63;
            float v;
            if (kk < 3) {
                v = __ldcg(&g_rs[(j0 + kk) * 64 + idx]);
            } else {
                int j = j0 + (kk - 3);
                v = 0.f;
                #pragma unroll
                for (int rb = 0; rb < 8; rb++) v += __ldcg(&g_csp[(j * 8 + rb) * 64 + idx]);
            }
            sinvC[i] = 1.0f / (v + 1e-5f);
        }
        // copy raw E matrices (aa1 needs E0,E1; aa2 needs all 3)
        int nmats = kind ? 3 : 2;
        for (int mat = 0; mat < nmats; mat++) {
            const float4* Eg = (const float4*)(g_E + (size_t)(j0 + mat) * 4096);
            float* Es = sm + mat * 64 * ESTRIDE;
            for (int i = tid; i < 1024; i += 256) {
                int n = i >> 4, mb = (i & 15) * 4;
                float4 v = __ldg(Eg + i);
                Es[n * ESTRIDE + mb + 0] = v.x;
                Es[n * ESTRIDE + mb + 1] = v.y;
                Es[n * ESTRIDE + mb + 2] = v.z;
                Es[n * ESTRIDE + mb + 3] = v.w;
            }
        }
        __syncthreads();
        // buf0 = A12_0 slice, pre-scaled by rinv1 (next mm's row scale)
        {
            int r = tid >> 6, m = tid & 63;
            buf0[r * BSTRIDE + m] = E0s[(r0 + r) * ESTRIDE + m]
                                    * sinvC[r0 + r] * sinvC[64 + m];
        }
        __syncthreads();

        float* res;
        if (kind == 0) {
            mm4v(buf0, E1s, false, sinvC + 256, buf1);  // P      -> *cinv1
            mm4v(buf1, E1s, true,  sinvC + 192, buf0);  // @A21_1 -> *cinv0
            mm4v(buf0, E0s, true,  nullptr,     buf1);  // @A21_0 = aa1
            res = buf1;
        } else {
            mm4v(buf0, E1s, false, sinvC + 128, buf1);  // P      -> *rinv2
            mm4v(buf1, E2s, false, sinvC + 320, buf0);  // @A12_2 -> *cinv2
            mm4v(buf0, E2s, true,  sinvC + 256, buf1);  // @A21_2 -> *cinv1
            mm4v(buf1, E1s, true,  sinvC + 192, buf0);  // @A21_1 -> *cinv0
            mm4v(buf0, E0s, true,  nullptr,     buf1);  // @A21_0 = aa2
            res = buf1;
        }

        // emit + loss
        {
            int r = tid >> 6, m = tid & 63;
            float* dst = out + aa_base + (size_t)(kind * B_ + b) * 4096;
            dst[(r0 + r) * 64 + m] = res[r * BSTRIDE + m];
            if (write_loss && tid < 4) {
                float s = 0.f;
                #pragma unroll 8
                for (int j = 0; j < 64; j++) s += res[tid * BSTRIDE + j];
                float diag = res[tid * BSTRIDE + (r0 + tid)] + 1e-20f;
                slloss[tid] = logf(s + 6.4e-19f) - logf(diag);
            }
            __syncthreads();
            if (write_loss && tid == 0) {
                float s = slloss[0] + slloss[1] + slloss[2] + slloss[3];
                atomicAdd(out, s * (1.0f / 128.0f));
            }
        }
    }
}

// ---------------- launch ----------------
extern "C" void kernel_launch(void* const* d_in, const int* in_sizes, int n_in,
                              void* d_out, int out_size) {
    const float* feats   = (const float*)d_in[0];
    const float* W_head  = (const float*)d_in[1];
    const int*   sp_mask = (const int*)  d_in[2];
    float* out = (float*)d_out;

    int aa_base    = (out_size > 2 * B_ * SP_ * SP_) ? 1 : 0;
    int write_loss = aa_base;

    cudaFuncSetAttribute(mega_kernel, cudaFuncAttributeMaxDynamicSharedMemorySize, SMEM_MEGA);

    fused_in_kernel<<<588, 256>>>(sp_mask, feats, W_head, out, write_loss);
    mega_kernel    <<<NBLK, 256, SMEM_MEGA>>>(out, aa_base, write_loss);
}